// round 3
// baseline (speedup 1.0000x reference)
#include <cuda_runtime.h>
#include <stdint.h>

#define NA 100000
#define NE 200000
#define NM 4096
#define DV 133
#define DE_ 14
#define DH 512
#define DIN 147      // DV + DE
#define KOUT 645     // DV + DH

// ---------------- static device scratch (no allocs allowed) ----------------
__device__ float g_H0[(size_t)NE * DH];   // pre-activation H0
__device__ float g_Ha[(size_t)NE * DH];   // current H
__device__ float g_Hb[(size_t)NE * DH];   // X = M[src] - H[rev]
__device__ float g_M [(size_t)NA * DH];   // per-atom segment sums
__device__ float g_msum[(size_t)NM * DH]; // per-mol sums
__device__ float g_cnt[NM];
__device__ float g_mu[DH];
__device__ float g_rs[DH];

// ---------------- utility kernels ----------------
__global__ void k_zero_M() {
    size_t i = (size_t)blockIdx.x * blockDim.x + threadIdx.x;
    if (i < (size_t)NA * DH) g_M[i] = 0.f;
}

__global__ void k_zero_mol() {
    size_t i = (size_t)blockIdx.x * blockDim.x + threadIdx.x;
    if (i < (size_t)NM * DH) g_msum[i] = 0.f;
    if (i < NM) g_cnt[i] = 0.f;
}

// scatter-add H rows into g_M[dst]
__global__ void k_scatter(const int* __restrict__ dst) {
    size_t i = (size_t)blockIdx.x * blockDim.x + threadIdx.x;
    size_t n = (size_t)NE * (DH / 4);
    if (i >= n) return;
    int e  = (int)(i >> 7);
    int c4 = (int)(i & 127);
    const float4* H4 = (const float4*)g_Ha;
    float4 v = H4[i];
    float* base = g_M + (size_t)dst[e] * DH + c4 * 4;
    atomicAdd(base + 0, v.x);
    atomicAdd(base + 1, v.y);
    atomicAdd(base + 2, v.z);
    atomicAdd(base + 3, v.w);
}

// X[e] = M[src[e]] - H[e^1]
__global__ void k_buildX(const int* __restrict__ src) {
    size_t i = (size_t)blockIdx.x * blockDim.x + threadIdx.x;
    size_t n = (size_t)NE * (DH / 4);
    if (i >= n) return;
    int e  = (int)(i >> 7);
    int c4 = (int)(i & 127);
    const float4* M4 = (const float4*)g_M;
    const float4* H4 = (const float4*)g_Ha;
    float4* X4 = (float4*)g_Hb;
    float4 m = M4[(size_t)src[e] * (DH / 4) + c4];
    float4 h = H4[(size_t)(e ^ 1) * (DH / 4) + c4];
    X4[i] = make_float4(m.x - h.x, m.y - h.y, m.z - h.z, m.w - h.w);
}

__global__ void k_counts(const int* __restrict__ batch) {
    int a = blockIdx.x * blockDim.x + threadIdx.x;
    if (a < NA) atomicAdd(&g_cnt[batch[a]], 1.f);
}

// ---------------- GEMM 1: H0 = [V[src]; E] @ W_i, Ha = relu(H0) ----------------
__global__ __launch_bounds__(256) void k_gemm_init(
    const float* __restrict__ V, const float* __restrict__ Ef,
    const int* __restrict__ src, const float* __restrict__ Wi)
{
    __shared__ float As[16][128];
    __shared__ float Bs[16][128];
    int tid = threadIdx.x, tx = tid & 15, ty = tid >> 4;
    int row0 = blockIdx.x * 128, col0 = blockIdx.y * 128;
    int ar = tid >> 1, ak = (tid & 1) * 8;
    int e = row0 + ar;
    bool val = e < NE;
    int s = val ? src[e] : 0;
    int bkk = tid >> 5;
    int bn = (tid & 31) * 4;

    float acc[8][8];
#pragma unroll
    for (int i = 0; i < 8; i++)
#pragma unroll
        for (int j = 0; j < 8; j++) acc[i][j] = 0.f;

    for (int kt = 0; kt < 10; kt++) {
        int k0 = kt * 16;
        __syncthreads();
#pragma unroll
        for (int u = 0; u < 8; u++) {
            int kg = k0 + ak + u;
            float v = 0.f;
            if (val && kg < DIN)
                v = (kg < DV) ? V[(size_t)s * DV + kg]
                              : Ef[(size_t)e * DE_ + (kg - DV)];
            As[ak + u][ar] = v;
        }
#pragma unroll
        for (int h = 0; h < 2; h++) {
            int kg = k0 + bkk + h * 8;
            float4 b = (kg < DIN) ? *(const float4*)&Wi[(size_t)kg * DH + col0 + bn]
                                  : make_float4(0.f, 0.f, 0.f, 0.f);
            *(float4*)&Bs[bkk + h * 8][bn] = b;
        }
        __syncthreads();
#pragma unroll
        for (int kk = 0; kk < 16; kk++) {
            float a[8], b[8];
            *(float4*)(a)     = *(float4*)&As[kk][ty * 8];
            *(float4*)(a + 4) = *(float4*)&As[kk][ty * 8 + 4];
            *(float4*)(b)     = *(float4*)&Bs[kk][tx * 8];
            *(float4*)(b + 4) = *(float4*)&Bs[kk][tx * 8 + 4];
#pragma unroll
            for (int i = 0; i < 8; i++)
#pragma unroll
                for (int j = 0; j < 8; j++) acc[i][j] += a[i] * b[j];
        }
    }
#pragma unroll
    for (int i = 0; i < 8; i++) {
        int er = row0 + ty * 8 + i;
        if (er < NE) {
            size_t base = (size_t)er * DH + col0 + tx * 8;
#pragma unroll
            for (int jq = 0; jq < 2; jq++) {
                float4 h0 = make_float4(acc[i][jq * 4], acc[i][jq * 4 + 1],
                                        acc[i][jq * 4 + 2], acc[i][jq * 4 + 3]);
                *(float4*)&g_H0[base + jq * 4] = h0;
                float4 r = make_float4(fmaxf(h0.x, 0.f), fmaxf(h0.y, 0.f),
                                       fmaxf(h0.z, 0.f), fmaxf(h0.w, 0.f));
                *(float4*)&g_Ha[base + jq * 4] = r;
            }
        }
    }
}

// ---------------- GEMM 2 (hot): Ha = relu(H0 + Hb @ W_h), K=N=512 ----------------
__global__ __launch_bounds__(256, 2) void k_gemm_update(const float* __restrict__ W)
{
    __shared__ float As[2][16][128];
    __shared__ float Bs[2][16][128];
    int tid = threadIdx.x, tx = tid & 15, ty = tid >> 4;
    int row0 = blockIdx.x * 128, col0 = blockIdx.y * 128;
    int ar = tid >> 1, ak = (tid & 1) * 8;
    int arow = row0 + ar;
    bool aval = arow < NE;
    const float* Ap = g_Hb + (size_t)(aval ? arow : 0) * DH;
    int bkk = tid >> 5;
    int bn = (tid & 31) * 4;

    float acc[8][8];
#pragma unroll
    for (int i = 0; i < 8; i++)
#pragma unroll
        for (int j = 0; j < 8; j++) acc[i][j] = 0.f;

    float4 z4 = make_float4(0.f, 0.f, 0.f, 0.f);
    float4 ra0, ra1, rb0, rb1;

    // prologue: tile 0
    ra0 = aval ? *(const float4*)&Ap[ak]     : z4;
    ra1 = aval ? *(const float4*)&Ap[ak + 4] : z4;
    rb0 = *(const float4*)&W[(size_t)(bkk) * DH + col0 + bn];
    rb1 = *(const float4*)&W[(size_t)(bkk + 8) * DH + col0 + bn];
    As[0][ak + 0][ar] = ra0.x; As[0][ak + 1][ar] = ra0.y;
    As[0][ak + 2][ar] = ra0.z; As[0][ak + 3][ar] = ra0.w;
    As[0][ak + 4][ar] = ra1.x; As[0][ak + 5][ar] = ra1.y;
    As[0][ak + 6][ar] = ra1.z; As[0][ak + 7][ar] = ra1.w;
    *(float4*)&Bs[0][bkk][bn] = rb0;
    *(float4*)&Bs[0][bkk + 8][bn] = rb1;
    __syncthreads();

    for (int kt = 0; kt < 32; kt++) {
        int buf = kt & 1;
        if (kt < 31) {
            int k0 = (kt + 1) * 16;
            ra0 = aval ? *(const float4*)&Ap[k0 + ak]     : z4;
            ra1 = aval ? *(const float4*)&Ap[k0 + ak + 4] : z4;
            rb0 = *(const float4*)&W[(size_t)(k0 + bkk) * DH + col0 + bn];
            rb1 = *(const float4*)&W[(size_t)(k0 + bkk + 8) * DH + col0 + bn];
        }
#pragma unroll
        for (int kk = 0; kk < 16; kk++) {
            float a[8], b[8];
            *(float4*)(a)     = *(float4*)&As[buf][kk][ty * 8];
            *(float4*)(a + 4) = *(float4*)&As[buf][kk][ty * 8 + 4];
            *(float4*)(b)     = *(float4*)&Bs[buf][kk][tx * 8];
            *(float4*)(b + 4) = *(float4*)&Bs[buf][kk][tx * 8 + 4];
#pragma unroll
            for (int i = 0; i < 8; i++)
#pragma unroll
                for (int j = 0; j < 8; j++) acc[i][j] += a[i] * b[j];
        }
        if (kt < 31) {
            int nb = buf ^ 1;
            As[nb][ak + 0][ar] = ra0.x; As[nb][ak + 1][ar] = ra0.y;
            As[nb][ak + 2][ar] = ra0.z; As[nb][ak + 3][ar] = ra0.w;
            As[nb][ak + 4][ar] = ra1.x; As[nb][ak + 5][ar] = ra1.y;
            As[nb][ak + 6][ar] = ra1.z; As[nb][ak + 7][ar] = ra1.w;
            *(float4*)&Bs[nb][bkk][bn] = rb0;
            *(float4*)&Bs[nb][bkk + 8][bn] = rb1;
        }
        __syncthreads();
    }
#pragma unroll
    for (int i = 0; i < 8; i++) {
        int er = row0 + ty * 8 + i;
        if (er < NE) {
            size_t base = (size_t)er * DH + col0 + tx * 8;
#pragma unroll
            for (int jq = 0; jq < 2; jq++) {
                float4 h0 = *(float4*)&g_H0[base + jq * 4];
                float4 o;
                o.x = fmaxf(h0.x + acc[i][jq * 4 + 0], 0.f);
                o.y = fmaxf(h0.y + acc[i][jq * 4 + 1], 0.f);
                o.z = fmaxf(h0.z + acc[i][jq * 4 + 2], 0.f);
                o.w = fmaxf(h0.w + acc[i][jq * 4 + 3], 0.f);
                *(float4*)&g_Ha[base + jq * 4] = o;
            }
        }
    }
}

// ---------------- GEMM 3: H_v = relu([V; M_v] @ W_o + b_o) -> atomic mol sums ----------------
__global__ __launch_bounds__(256) void k_gemm_out(
    const float* __restrict__ V, const float* __restrict__ Wo,
    const float* __restrict__ bo, const int* __restrict__ batch)
{
    __shared__ float As[16][128];
    __shared__ float Bs[16][128];
    int tid = threadIdx.x, tx = tid & 15, ty = tid >> 4;
    int row0 = blockIdx.x * 128, col0 = blockIdx.y * 128;
    int ar = tid >> 1, ak = (tid & 1) * 8;
    int a0 = row0 + ar;
    bool val = a0 < NA;
    int bkk = tid >> 5;
    int bn = (tid & 31) * 4;

    float acc[8][8];
#pragma unroll
    for (int i = 0; i < 8; i++)
#pragma unroll
        for (int j = 0; j < 8; j++) acc[i][j] = 0.f;

    for (int kt = 0; kt < 41; kt++) {   // ceil(645/16)
        int k0 = kt * 16;
        __syncthreads();
#pragma unroll
        for (int u = 0; u < 8; u++) {
            int kg = k0 + ak + u;
            float v = 0.f;
            if (val && kg < KOUT)
                v = (kg < DV) ? V[(size_t)a0 * DV + kg]
                              : g_M[(size_t)a0 * DH + (kg - DV)];
            As[ak + u][ar] = v;
        }
#pragma unroll
        for (int h = 0; h < 2; h++) {
            int kg = k0 + bkk + h * 8;
            float4 b = (kg < KOUT) ? *(const float4*)&Wo[(size_t)kg * DH + col0 + bn]
                                   : make_float4(0.f, 0.f, 0.f, 0.f);
            *(float4*)&Bs[bkk + h * 8][bn] = b;
        }
        __syncthreads();
#pragma unroll
        for (int kk = 0; kk < 16; kk++) {
            float a[8], b[8];
            *(float4*)(a)     = *(float4*)&As[kk][ty * 8];
            *(float4*)(a + 4) = *(float4*)&As[kk][ty * 8 + 4];
            *(float4*)(b)     = *(float4*)&Bs[kk][tx * 8];
            *(float4*)(b + 4) = *(float4*)&Bs[kk][tx * 8 + 4];
#pragma unroll
            for (int i = 0; i < 8; i++)
#pragma unroll
                for (int j = 0; j < 8; j++) acc[i][j] += a[i] * b[j];
        }
    }
#pragma unroll
    for (int i = 0; i < 8; i++) {
        int a2 = row0 + ty * 8 + i;
        if (a2 < NA) {
            int mol = batch[a2];
            size_t base = (size_t)mol * DH + col0 + tx * 8;
#pragma unroll
            for (int j = 0; j < 8; j++) {
                float h = fmaxf(acc[i][j] + bo[col0 + tx * 8 + j], 0.f);
                atomicAdd(&g_msum[base + j], h);
            }
        }
    }
}

// ---------------- batchnorm stats + apply ----------------
__global__ void k_stats() {
    int c = blockIdx.x * blockDim.x + threadIdx.x;  // 512 threads total
    if (c >= DH) return;
    float s = 0.f, ss = 0.f;
    for (int m = 0; m < NM; m++) {
        float inv = 1.f / fmaxf(g_cnt[m], 1.f);
        float v = g_msum[(size_t)m * DH + c] * inv;
        s += v;
        ss += v * v;
    }
    float mu = s * (1.f / NM);
    g_mu[c] = mu;
    g_rs[c] = rsqrtf(ss * (1.f / NM) - mu * mu + 1e-5f);
}

__global__ void k_bn(const float* __restrict__ gamma, const float* __restrict__ beta,
                     float* __restrict__ out) {
    int i = blockIdx.x * blockDim.x + threadIdx.x;
    if (i < NM * DH) {
        int m = i >> 9, c = i & 511;
        float h = g_msum[i] / fmaxf(g_cnt[m], 1.f);
        out[i] = (h - g_mu[c]) * g_rs[c] * gamma[c] + beta[c];
    }
}

// ---------------- launch ----------------
extern "C" void kernel_launch(void* const* d_in, const int* in_sizes, int n_in,
                              void* d_out, int out_size) {
    const float* V     = (const float*)d_in[0];
    const float* Ef    = (const float*)d_in[1];
    const int*   esrc  = (const int*)d_in[2];
    const int*   edst  = (const int*)d_in[3];
    const int*   batch = (const int*)d_in[4];
    const float* Wi    = (const float*)d_in[5];
    const float* Wh    = (const float*)d_in[6];
    const float* Wo    = (const float*)d_in[7];
    const float* bo    = (const float*)d_in[8];
    const float* gamma = (const float*)d_in[9];
    const float* beta  = (const float*)d_in[10];
    float* out = (float*)d_out;

    dim3 ge((NE + 127) / 128, 4);
    dim3 ga((NA + 127) / 128, 4);
    int scatter_blocks = (int)(((size_t)NE * (DH / 4) + 255) / 256);
    int zeroM_blocks   = (int)(((size_t)NA * DH + 255) / 256);

    // H0 = [V[src]; E] @ W_i ; Ha = relu(H0)
    k_gemm_init<<<ge, 256>>>(V, Ef, esrc, Wi);

    for (int it = 0; it < 2; it++) {
        k_zero_M<<<zeroM_blocks, 256>>>();
        k_scatter<<<scatter_blocks, 256>>>(edst);
        k_buildX<<<scatter_blocks, 256>>>(esrc);
        k_gemm_update<<<ge, 256>>>(Wh);
    }

    // final aggregation to atoms
    k_zero_M<<<zeroM_blocks, 256>>>();
    k_scatter<<<scatter_blocks, 256>>>(edst);

    // mol sums / counts
    k_zero_mol<<<(NM * DH + 255) / 256, 256>>>();
    k_counts<<<(NA + 255) / 256, 256>>>(batch);
    k_gemm_out<<<ga, 256>>>(V, Wo, bo, batch);

    // batchnorm
    k_stats<<<4, 128>>>();
    k_bn<<<(NM * DH + 255) / 256, 256>>>(gamma, beta, out);
}

// round 6
// speedup vs baseline: 1.0746x; 1.0746x over previous
#include <cuda_runtime.h>
#include <stdint.h>

#define NA 100000
#define NE 200000
#define NM 4096
#define DV 133
#define DE_ 14
#define DH 512
#define DIN 147      // DV + DE
#define KOUT 645     // DV + DH

// packed-f32x2 helpers (sm_100+ PTX; ptxas will not auto-fuse from C++)
#define FMA2(d, a, b)   asm("fma.rn.f32x2 %0, %1, %2, %0;" : "+l"(d) : "l"(a), "l"(b))
#define BCAST2(d, s)    asm("mov.b64 %0, {%1, %1};" : "=l"(d) : "f"(s))
#define UNPK2(lo, hi, s) asm("mov.b64 {%0, %1}, %2;" : "=f"(lo), "=f"(hi) : "l"(s))

// ---------------- static device scratch (no allocs allowed) ----------------
__device__ float g_H0[(size_t)NE * DH];   // pre-activation H0
__device__ float g_Ha[(size_t)NE * DH];   // current H
__device__ float g_Hb[(size_t)NE * DH];   // X = M[src] - H[rev]
__device__ float g_M [(size_t)NA * DH];   // per-atom segment sums
__device__ float g_msum[(size_t)NM * DH]; // per-mol sums
__device__ float g_cnt[NM];
__device__ float g_mu[DH];
__device__ float g_rs[DH];

// ---------------- utility kernels ----------------
__global__ void k_zero_M() {
    size_t i = (size_t)blockIdx.x * blockDim.x + threadIdx.x;
    if (i < (size_t)NA * (DH / 4))
        ((float4*)g_M)[i] = make_float4(0.f, 0.f, 0.f, 0.f);
}

__global__ void k_zero_mol() {
    size_t i = (size_t)blockIdx.x * blockDim.x + threadIdx.x;
    if (i < (size_t)NM * (DH / 4))
        ((float4*)g_msum)[i] = make_float4(0.f, 0.f, 0.f, 0.f);
    if (i < NM) g_cnt[i] = 0.f;
}

// scatter-add H rows into g_M[dst]
__global__ void k_scatter(const int* __restrict__ dst) {
    size_t i = (size_t)blockIdx.x * blockDim.x + threadIdx.x;
    size_t n = (size_t)NE * (DH / 4);
    if (i >= n) return;
    int e  = (int)(i >> 7);
    int c4 = (int)(i & 127);
    const float4* H4 = (const float4*)g_Ha;
    float4 v = H4[i];
    float* base = g_M + (size_t)dst[e] * DH + c4 * 4;
    atomicAdd(base + 0, v.x);
    atomicAdd(base + 1, v.y);
    atomicAdd(base + 2, v.z);
    atomicAdd(base + 3, v.w);
}

// X[e] = M[src[e]] - H[e^1]
__global__ void k_buildX(const int* __restrict__ src) {
    size_t i = (size_t)blockIdx.x * blockDim.x + threadIdx.x;
    size_t n = (size_t)NE * (DH / 4);
    if (i >= n) return;
    int e  = (int)(i >> 7);
    int c4 = (int)(i & 127);
    const float4* M4 = (const float4*)g_M;
    const float4* H4 = (const float4*)g_Ha;
    float4* X4 = (float4*)g_Hb;
    float4 m = M4[(size_t)src[e] * (DH / 4) + c4];
    float4 h = H4[(size_t)(e ^ 1) * (DH / 4) + c4];
    X4[i] = make_float4(m.x - h.x, m.y - h.y, m.z - h.z, m.w - h.w);
}

__global__ void k_counts(const int* __restrict__ batch) {
    int a = blockIdx.x * blockDim.x + threadIdx.x;
    if (a < NA) atomicAdd(&g_cnt[batch[a]], 1.f);
}

// ---------------- GEMM 1: H0 = [V[src]; E] @ W_i, Ha = relu(H0) ----------------
__global__ __launch_bounds__(256) void k_gemm_init(
    const float* __restrict__ V, const float* __restrict__ Ef,
    const int* __restrict__ src, const float* __restrict__ Wi)
{
    __shared__ float As[16][128];
    __shared__ float Bs[16][128];
    int tid = threadIdx.x, tx = tid & 15, ty = tid >> 4;
    int row0 = blockIdx.x * 128, col0 = blockIdx.y * 128;
    int ar = tid >> 1, ak = (tid & 1) * 8;
    int e = row0 + ar;
    bool val = e < NE;
    int s = val ? src[e] : 0;
    int bkk = tid >> 5;
    int bn = (tid & 31) * 4;

    unsigned long long acc[8][4];
#pragma unroll
    for (int i = 0; i < 8; i++)
#pragma unroll
        for (int q = 0; q < 4; q++) acc[i][q] = 0ULL;

    for (int kt = 0; kt < 10; kt++) {
        int k0 = kt * 16;
        __syncthreads();
#pragma unroll
        for (int u = 0; u < 8; u++) {
            int kg = k0 + ak + u;
            float v = 0.f;
            if (val && kg < DIN)
                v = (kg < DV) ? V[(size_t)s * DV + kg]
                              : Ef[(size_t)e * DE_ + (kg - DV)];
            As[ak + u][ar] = v;
        }
#pragma unroll
        for (int h = 0; h < 2; h++) {
            int kg = k0 + bkk + h * 8;
            float4 b = (kg < DIN) ? *(const float4*)&Wi[(size_t)kg * DH + col0 + bn]
                                  : make_float4(0.f, 0.f, 0.f, 0.f);
            *(float4*)&Bs[bkk + h * 8][bn] = b;
        }
        __syncthreads();
#pragma unroll
        for (int kk = 0; kk < 16; kk++) {
            float a[8];
            *(float4*)(a)     = *(float4*)&As[kk][ty * 8];
            *(float4*)(a + 4) = *(float4*)&As[kk][ty * 8 + 4];
            ulonglong2 b0 = *(const ulonglong2*)&Bs[kk][tx * 8];
            ulonglong2 b1 = *(const ulonglong2*)&Bs[kk][tx * 8 + 4];
#pragma unroll
            for (int i = 0; i < 8; i++) {
                unsigned long long aa; BCAST2(aa, a[i]);
                FMA2(acc[i][0], aa, b0.x);
                FMA2(acc[i][1], aa, b0.y);
                FMA2(acc[i][2], aa, b1.x);
                FMA2(acc[i][3], aa, b1.y);
            }
        }
    }
#pragma unroll
    for (int i = 0; i < 8; i++) {
        int er = row0 + ty * 8 + i;
        if (er < NE) {
            size_t base = (size_t)er * DH + col0 + tx * 8;
            float r[8];
#pragma unroll
            for (int q = 0; q < 4; q++) UNPK2(r[2 * q], r[2 * q + 1], acc[i][q]);
#pragma unroll
            for (int jq = 0; jq < 2; jq++) {
                float4 h0 = make_float4(r[jq * 4], r[jq * 4 + 1],
                                        r[jq * 4 + 2], r[jq * 4 + 3]);
                *(float4*)&g_H0[base + jq * 4] = h0;
                float4 rr = make_float4(fmaxf(h0.x, 0.f), fmaxf(h0.y, 0.f),
                                        fmaxf(h0.z, 0.f), fmaxf(h0.w, 0.f));
                *(float4*)&g_Ha[base + jq * 4] = rr;
            }
        }
    }
}

// ---------------- GEMM 2 (hot): Ha = relu(H0 + Hb @ W_h), K=N=512 ----------------
__global__ __launch_bounds__(256, 2) void k_gemm_update(const float* __restrict__ W)
{
    __shared__ float As[2][16][128];
    __shared__ float Bs[2][16][128];
    int tid = threadIdx.x, tx = tid & 15, ty = tid >> 4;
    int row0 = blockIdx.x * 128, col0 = blockIdx.y * 128;
    int ar = tid >> 1, ak = (tid & 1) * 8;
    int arow = row0 + ar;
    bool aval = arow < NE;
    const float* Ap = g_Hb + (size_t)(aval ? arow : 0) * DH;
    int bkk = tid >> 5;
    int bn = (tid & 31) * 4;

    unsigned long long acc[8][4];
#pragma unroll
    for (int i = 0; i < 8; i++)
#pragma unroll
        for (int q = 0; q < 4; q++) acc[i][q] = 0ULL;

    float4 z4 = make_float4(0.f, 0.f, 0.f, 0.f);
    float4 ra0, ra1, rb0, rb1;

    // prologue: tile 0
    ra0 = aval ? *(const float4*)&Ap[ak]     : z4;
    ra1 = aval ? *(const float4*)&Ap[ak + 4] : z4;
    rb0 = *(const float4*)&W[(size_t)(bkk) * DH + col0 + bn];
    rb1 = *(const float4*)&W[(size_t)(bkk + 8) * DH + col0 + bn];
    As[0][ak + 0][ar] = ra0.x; As[0][ak + 1][ar] = ra0.y;
    As[0][ak + 2][ar] = ra0.z; As[0][ak + 3][ar] = ra0.w;
    As[0][ak + 4][ar] = ra1.x; As[0][ak + 5][ar] = ra1.y;
    As[0][ak + 6][ar] = ra1.z; As[0][ak + 7][ar] = ra1.w;
    *(float4*)&Bs[0][bkk][bn] = rb0;
    *(float4*)&Bs[0][bkk + 8][bn] = rb1;
    __syncthreads();

    for (int kt = 0; kt < 32; kt++) {
        int buf = kt & 1;
        if (kt < 31) {
            int k0 = (kt + 1) * 16;
            ra0 = aval ? *(const float4*)&Ap[k0 + ak]     : z4;
            ra1 = aval ? *(const float4*)&Ap[k0 + ak + 4] : z4;
            rb0 = *(const float4*)&W[(size_t)(k0 + bkk) * DH + col0 + bn];
            rb1 = *(const float4*)&W[(size_t)(k0 + bkk + 8) * DH + col0 + bn];
        }
#pragma unroll
        for (int kk = 0; kk < 16; kk++) {
            float a[8];
            *(float4*)(a)     = *(float4*)&As[buf][kk][ty * 8];
            *(float4*)(a + 4) = *(float4*)&As[buf][kk][ty * 8 + 4];
            ulonglong2 b0 = *(const ulonglong2*)&Bs[buf][kk][tx * 8];
            ulonglong2 b1 = *(const ulonglong2*)&Bs[buf][kk][tx * 8 + 4];
#pragma unroll
            for (int i = 0; i < 8; i++) {
                unsigned long long aa; BCAST2(aa, a[i]);
                FMA2(acc[i][0], aa, b0.x);
                FMA2(acc[i][1], aa, b0.y);
                FMA2(acc[i][2], aa, b1.x);
                FMA2(acc[i][3], aa, b1.y);
            }
        }
        if (kt < 31) {
            int nb = buf ^ 1;
            As[nb][ak + 0][ar] = ra0.x; As[nb][ak + 1][ar] = ra0.y;
            As[nb][ak + 2][ar] = ra0.z; As[nb][ak + 3][ar] = ra0.w;
            As[nb][ak + 4][ar] = ra1.x; As[nb][ak + 5][ar] = ra1.y;
            As[nb][ak + 6][ar] = ra1.z; As[nb][ak + 7][ar] = ra1.w;
            *(float4*)&Bs[nb][bkk][bn] = rb0;
            *(float4*)&Bs[nb][bkk + 8][bn] = rb1;
        }
        __syncthreads();
    }
#pragma unroll
    for (int i = 0; i < 8; i++) {
        int er = row0 + ty * 8 + i;
        if (er < NE) {
            size_t base = (size_t)er * DH + col0 + tx * 8;
            float r[8];
#pragma unroll
            for (int q = 0; q < 4; q++) UNPK2(r[2 * q], r[2 * q + 1], acc[i][q]);
#pragma unroll
            for (int jq = 0; jq < 2; jq++) {
                float4 h0 = *(float4*)&g_H0[base + jq * 4];
                float4 o;
                o.x = fmaxf(h0.x + r[jq * 4 + 0], 0.f);
                o.y = fmaxf(h0.y + r[jq * 4 + 1], 0.f);
                o.z = fmaxf(h0.z + r[jq * 4 + 2], 0.f);
                o.w = fmaxf(h0.w + r[jq * 4 + 3], 0.f);
                *(float4*)&g_Ha[base + jq * 4] = o;
            }
        }
    }
}

// ---------------- GEMM 3: H_v = relu([V; M_v] @ W_o + b_o) -> atomic mol sums ----------------
__global__ __launch_bounds__(256) void k_gemm_out(
    const float* __restrict__ V, const float* __restrict__ Wo,
    const float* __restrict__ bo, const int* __restrict__ batch)
{
    __shared__ float As[16][128];
    __shared__ float Bs[16][128];
    int tid = threadIdx.x, tx = tid & 15, ty = tid >> 4;
    int row0 = blockIdx.x * 128, col0 = blockIdx.y * 128;
    int ar = tid >> 1, ak = (tid & 1) * 8;
    int a0 = row0 + ar;
    bool val = a0 < NA;
    int bkk = tid >> 5;
    int bn = (tid & 31) * 4;

    unsigned long long acc[8][4];
#pragma unroll
    for (int i = 0; i < 8; i++)
#pragma unroll
        for (int q = 0; q < 4; q++) acc[i][q] = 0ULL;

    for (int kt = 0; kt < 41; kt++) {   // ceil(645/16)
        int k0 = kt * 16;
        __syncthreads();
#pragma unroll
        for (int u = 0; u < 8; u++) {
            int kg = k0 + ak + u;
            float v = 0.f;
            if (val && kg < KOUT)
                v = (kg < DV) ? V[(size_t)a0 * DV + kg]
                              : g_M[(size_t)a0 * DH + (kg - DV)];
            As[ak + u][ar] = v;
        }
#pragma unroll
        for (int h = 0; h < 2; h++) {
            int kg = k0 + bkk + h * 8;
            float4 b = (kg < KOUT) ? *(const float4*)&Wo[(size_t)kg * DH + col0 + bn]
                                   : make_float4(0.f, 0.f, 0.f, 0.f);
            *(float4*)&Bs[bkk + h * 8][bn] = b;
        }
        __syncthreads();
#pragma unroll
        for (int kk = 0; kk < 16; kk++) {
            float a[8];
            *(float4*)(a)     = *(float4*)&As[kk][ty * 8];
            *(float4*)(a + 4) = *(float4*)&As[kk][ty * 8 + 4];
            ulonglong2 b0 = *(const ulonglong2*)&Bs[kk][tx * 8];
            ulonglong2 b1 = *(const ulonglong2*)&Bs[kk][tx * 8 + 4];
#pragma unroll
            for (int i = 0; i < 8; i++) {
                unsigned long long aa; BCAST2(aa, a[i]);
                FMA2(acc[i][0], aa, b0.x);
                FMA2(acc[i][1], aa, b0.y);
                FMA2(acc[i][2], aa, b1.x);
                FMA2(acc[i][3], aa, b1.y);
            }
        }
    }
#pragma unroll
    for (int i = 0; i < 8; i++) {
        int a2 = row0 + ty * 8 + i;
        if (a2 < NA) {
            int mol = batch[a2];
            size_t base = (size_t)mol * DH + col0 + tx * 8;
            float r[8];
#pragma unroll
            for (int q = 0; q < 4; q++) UNPK2(r[2 * q], r[2 * q + 1], acc[i][q]);
#pragma unroll
            for (int j = 0; j < 8; j++) {
                float h = fmaxf(r[j] + bo[col0 + tx * 8 + j], 0.f);
                atomicAdd(&g_msum[base + j], h);
            }
        }
    }
}

// ---------------- batchnorm stats + apply ----------------
__global__ void k_stats() {
    int c = blockIdx.x * blockDim.x + threadIdx.x;  // 512 threads total
    if (c >= DH) return;
    float s = 0.f, ss = 0.f;
    for (int m = 0; m < NM; m++) {
        float inv = 1.f / fmaxf(g_cnt[m], 1.f);
        float v = g_msum[(size_t)m * DH + c] * inv;
        s += v;
        ss += v * v;
    }
    float mu = s * (1.f / NM);
    g_mu[c] = mu;
    g_rs[c] = rsqrtf(ss * (1.f / NM) - mu * mu + 1e-5f);
}

__global__ void k_bn(const float* __restrict__ gamma, const float* __restrict__ beta,
                     float* __restrict__ out) {
    int i = blockIdx.x * blockDim.x + threadIdx.x;
    if (i < NM * DH) {
        int m = i >> 9, c = i & 511;
        float h = g_msum[i] / fmaxf(g_cnt[m], 1.f);
        out[i] = (h - g_mu[c]) * g_rs[c] * gamma[c] + beta[c];
    }
}

// ---------------- launch ----------------
extern "C" void kernel_launch(void* const* d_in, const int* in_sizes, int n_in,
                              void* d_out, int out_size) {
    const float* V     = (const float*)d_in[0];
    const float* Ef    = (const float*)d_in[1];
    const int*   esrc  = (const int*)d_in[2];
    const int*   edst  = (const int*)d_in[3];
    const int*   batch = (const int*)d_in[4];
    const float* Wi    = (const float*)d_in[5];
    const float* Wh    = (const float*)d_in[6];
    const float* Wo    = (const float*)d_in[7];
    const float* bo    = (const float*)d_in[8];
    const float* gamma = (const float*)d_in[9];
    const float* beta  = (const float*)d_in[10];
    float* out = (float*)d_out;

    dim3 ge((NE + 127) / 128, 4);
    dim3 ga((NA + 127) / 128, 4);
    int scatter_blocks = (int)(((size_t)NE * (DH / 4) + 255) / 256);
    int zeroM_blocks   = (int)(((size_t)NA * (DH / 4) + 255) / 256);

    // H0 = [V[src]; E] @ W_i ; Ha = relu(H0)
    k_gemm_init<<<ge, 256>>>(V, Ef, esrc, Wi);

    for (int it = 0; it < 2; it++) {
        k_zero_M<<<zeroM_blocks, 256>>>();
        k_scatter<<<scatter_blocks, 256>>>(edst);
        k_buildX<<<scatter_blocks, 256>>>(esrc);
        k_gemm_update<<<ge, 256>>>(Wh);
    }

    // final aggregation to atoms
    k_zero_M<<<zeroM_blocks, 256>>>();
    k_scatter<<<scatter_blocks, 256>>>(edst);

    // mol sums / counts
    k_zero_mol<<<(NM * (DH / 4) + 255) / 256, 256>>>();
    k_counts<<<(NA + 255) / 256, 256>>>(batch);
    k_gemm_out<<<ga, 256>>>(V, Wo, bo, batch);

    // batchnorm
    k_stats<<<4, 128>>>();
    k_bn<<<(NM * DH + 255) / 256, 256>>>(gamma, beta, out);
}